// round 14
// baseline (speedup 1.0000x reference)
#include <cuda_runtime.h>

typedef unsigned long long ull;

#define NROWS 4194304
#define NPAIR (NROWS/2)
#define NGRP4 (NROWS/4)
#define NBLK  148
#define NTHR  640
#define TT    (NBLK*NTHR)
#define NWARP (NTHR/32)

// 80 MB activation scratch, SoA: g_Z[f*NROWS + row]
__device__ float g_Z[(size_t)5 * NROWS];
// per-round block partial sums (double-buffered by round parity)
__device__ float g_part[2][NBLK * 20];
__device__ unsigned g_cnt = 0;
__device__ unsigned g_gen = 0;

// ---------------- packed f32x2 helpers ----------------
__device__ __forceinline__ ull pk(float lo, float hi) {
    ull r; asm("mov.b64 %0,{%1,%2};" : "=l"(r) : "f"(lo), "f"(hi)); return r;
}
__device__ __forceinline__ void upk(ull v, float& lo, float& hi) {
    asm("mov.b64 {%0,%1},%2;" : "=f"(lo), "=f"(hi) : "l"(v));
}
__device__ __forceinline__ ull fma2(ull a, ull b, ull c) {
    ull d; asm("fma.rn.f32x2 %0,%1,%2,%3;" : "=l"(d) : "l"(a), "l"(b), "l"(c)); return d;
}
__device__ __forceinline__ ull add2(ull a, ull b) {
    ull d; asm("add.rn.f32x2 %0,%1,%2;" : "=l"(d) : "l"(a), "l"(b)); return d;
}
// relu on both packed halves (no packed max in PTX)
__device__ __forceinline__ ull relu2(ull a) {
    float lo, hi; upk(a, lo, hi);
    return pk(fmaxf(lo, 0.f), fmaxf(hi, 0.f));
}

// ---------------- L2 cache policies (policy-operand form) ----------------
__device__ __forceinline__ ull mkpolicy_evict_last() {
    ull p; asm("createpolicy.fractional.L2::evict_last.b64 %0, 1.0;" : "=l"(p)); return p;
}
__device__ __forceinline__ ull mkpolicy_evict_first() {
    ull p; asm("createpolicy.fractional.L2::evict_first.b64 %0, 1.0;" : "=l"(p)); return p;
}

// ---------------- grid barrier (generation counter, replay-safe) ----------------
__device__ __forceinline__ void grid_barrier() {
    __threadfence();
    __syncthreads();
    if (threadIdx.x == 0) {
        unsigned my = *((volatile unsigned*)&g_gen);
        unsigned t = atomicAdd(&g_cnt, 1u);
        if (t == (unsigned)(NBLK - 1)) {
            g_cnt = 0u;
            __threadfence();
            atomicAdd(&g_gen, 1u);
        } else {
            while (*((volatile unsigned*)&g_gen) == my) { __nanosleep(64); }
        }
    }
    __syncthreads();
    __threadfence();
}

// ---------------- Z access: one packed pair (2 rows) per thread ----------------
__device__ __forceinline__ void loadZ1(int g, ull z[5], ull pol) {
#pragma unroll
    for (int f = 0; f < 5; f++) {
        const ull* p = (const ull*)&g_Z[(size_t)f * NROWS + 2 * (size_t)g];
        asm volatile("ld.global.L2::cache_hint.u64 %0, [%1], %2;"
                     : "=l"(z[f]) : "l"(p), "l"(pol));
    }
}
__device__ __forceinline__ void storeZ1(int g, const ull z[5], ull pol) {
#pragma unroll
    for (int f = 0; f < 5; f++) {
        ull* p = (ull*)&g_Z[(size_t)f * NROWS + 2 * (size_t)g];
        asm volatile("st.global.L2::cache_hint.u64 [%0], %1, %2;"
                     :: "l"(p), "l"(z[f]), "l"(pol) : "memory");
    }
}
// pass 0 only: store 2 adjacent pairs (4 rows) at once
__device__ __forceinline__ void storeZ2w(int g4, const ull a[5], const ull b[5], ull pol) {
#pragma unroll
    for (int f = 0; f < 5; f++) {
        ull* p = (ull*)&g_Z[(size_t)f * NROWS + 4 * (size_t)g4];
        asm volatile("st.global.L2::cache_hint.v2.u64 [%0], {%1,%2}, %3;"
                     :: "l"(p), "l"(a[f]), "l"(b[f]), "l"(pol) : "memory");
    }
}
__device__ __forceinline__ float4 load_x4_stream(const float4* p, ull pol) {
    float4 v;
    asm volatile("ld.global.nc.L2::cache_hint.v4.f32 {%0,%1,%2,%3}, [%4], %5;"
                 : "=f"(v.x), "=f"(v.y), "=f"(v.z), "=f"(v.w) : "l"(p), "l"(pol));
    return v;
}

// ---------------- stats accumulation: 5 means + 15 upper-tri 2nd moments ----------------
__device__ __forceinline__ void st2(ull acc[20], const ull p[5]) {
#pragma unroll
    for (int i = 0; i < 5; i++) acc[i] = add2(acc[i], p[i]);
    int c = 5;
#pragma unroll
    for (int i = 0; i < 5; i++) {
#pragma unroll
        for (int k = i; k < 5; k++) { acc[c] = fma2(p[i], p[k], acc[c]); c++; }
    }
}

// load one padded weight row (stride 6) as 2xLDS.128 + 1xLDS.64
__device__ __forceinline__ void ldrow(const ull* sW, int j, ull w[5]) {
    const ulonglong2* r = (const ulonglong2*)(sW + j * 6);
    ulonglong2 w01 = r[0], w23 = r[1];
    w[0] = w01.x; w[1] = w01.y; w[2] = w23.x; w[3] = w23.y; w[4] = sW[j * 6 + 4];
}

// h = relu(W z + b), one packed pair
__device__ __forceinline__ void aff5r(const ull* sW, const ull* sB, const ull in[5], ull out[5]) {
#pragma unroll
    for (int j = 0; j < 5; j++) {
        ull w[5]; ldrow(sW, j, w);
        ull t = sB[j];
#pragma unroll
        for (int i = 0; i < 5; i++) t = fma2(w[i], in[i], t);
        out[j] = relu2(t);
    }
}

// ---------------- deterministic block reduction -> g_part[slot] ----------------
__device__ __forceinline__ void reduce_store(ull acc[20], int slot, float (*swr)[20]) {
    int tid = threadIdx.x;
    float a[20];
#pragma unroll
    for (int j = 0; j < 20; j++) { float lo, hi; upk(acc[j], lo, hi); a[j] = lo + hi; }
#pragma unroll
    for (int j = 0; j < 20; j++) {
#pragma unroll
        for (int o = 16; o > 0; o >>= 1) a[j] += __shfl_down_sync(0xffffffffu, a[j], o);
    }
    int w = tid >> 5, l = tid & 31;
    if (l == 0) {
#pragma unroll
        for (int j = 0; j < 20; j++) swr[w][j] = a[j];
    }
    __syncthreads();
    if (tid < 20) {
        float t = 0.f;
#pragma unroll
        for (int k = 0; k < NWARP; k++) t += swr[k][tid];
        g_part[slot][blockIdx.x * 20 + tid] = t;
    }
}

// ---------------- BN fold: exact affine from input stats (writes stride-6 rows) ----------------
__device__ __forceinline__ void fold_affine(
    int slot, int J,
    const float* __restrict__ W, const float* __restrict__ B,
    const float* __restrict__ G, const float* __restrict__ Bt,
    ull* sW, ull* sB, float* sS)
{
    int tid = threadIdx.x;
    if (tid < 20) {
        float t = 0.f;
        for (int k = 0; k < NBLK; k++) t += g_part[slot][k * 20 + tid];
        sS[tid] = t;
    }
    __syncthreads();
    if (tid < J) {
        const double inv = 1.0 / (double)NROWS;
        double m[5], w[5];
#pragma unroll
        for (int i = 0; i < 5; i++) { m[i] = (double)sS[i] * inv; w[i] = (double)W[tid * 5 + i]; }
        double mu = (double)B[tid];
#pragma unroll
        for (int i = 0; i < 5; i++) mu += w[i] * m[i];
        double var = 0.0; int c = 5;
        for (int i = 0; i < 5; i++)
            for (int k = i; k < 5; k++) {
                double C = (double)sS[c] * inv - m[i] * m[k];
                var += (i == k ? w[i] * w[k] : 2.0 * w[i] * w[k]) * C;
                c++;
            }
        double rstd = rsqrt(var + 1e-5);
        float sc = (float)((double)G[tid] * rstd);
#pragma unroll
        for (int i = 0; i < 5; i++) { float wv = W[tid * 5 + i] * sc; sW[tid * 6 + i] = pk(wv, wv); }
        sW[tid * 6 + 5] = 0ull;  // padding
        float bv = (float)(((double)B[tid] - mu) * rstd * (double)G[tid] + (double)Bt[tid]);
        sB[tid] = pk(bv, bv);
    }
    __syncthreads();
}

// ---------------- the whole net in one persistent kernel ----------------
__global__ void __launch_bounds__(NTHR, 1) net_kernel(
    const float* __restrict__ x,
    const float* __restrict__ lw,  const float* __restrict__ lb,
    const float* __restrict__ skw, const float* __restrict__ skb,
    const float* __restrict__ bng, const float* __restrict__ bnb,
    const float* __restrict__ l9w, const float* __restrict__ l9b,
    const float* __restrict__ b9g, const float* __restrict__ b9b,
    const float* __restrict__ l10w, const float* __restrict__ l10b,
    float* __restrict__ out)
{
    __shared__ ull sWi[30], sBi[5], sWj[30], sBj[5], sSkW[30];
    __shared__ float swr[NWARP][20];
    __shared__ float sS[20];

    const int tid = threadIdx.x;
    const int gt0 = blockIdx.x * NTHR + tid;
    const ull POL = mkpolicy_evict_last();
    const ull POLF = mkpolicy_evict_first();

    ull acc[20];

    // ---- pass 0: transpose x (AoS, streaming) -> g_Z (SoA, pinned) + stats(x); 4 rows/thread
#pragma unroll
    for (int q = 0; q < 20; q++) acc[q] = 0ull;
    for (int g = gt0; g < NGRP4; g += TT) {
        const float4* p = (const float4*)(x + (size_t)20 * g);
        float4 A = load_x4_stream(p + 0, POLF), Bq = load_x4_stream(p + 1, POLF),
               Cq = load_x4_stream(p + 2, POLF), Dq = load_x4_stream(p + 3, POLF),
               Eq = load_x4_stream(p + 4, POLF);
        ull a[5], b[5];
        a[0] = pk(A.x,  Bq.y); a[1] = pk(A.y,  Bq.z); a[2] = pk(A.z,  Bq.w);
        a[3] = pk(A.w,  Cq.x); a[4] = pk(Bq.x, Cq.y);
        b[0] = pk(Cq.z, Dq.w); b[1] = pk(Cq.w, Eq.x); b[2] = pk(Dq.x, Eq.y);
        b[3] = pk(Dq.y, Eq.z); b[4] = pk(Dq.z, Eq.w);
        storeZ2w(g, a, b, POL);
        st2(acc, a); st2(acc, b);
    }
    reduce_store(acc, 0, swr);
    grid_barrier();

    int slot = 0;
    for (int blk = 0; blk < 4; blk++) {
        const int li = 2 * blk, lj = li + 1;
        fold_affine(slot, 5, lw + li * 25, lb + li * 5, bng + li * 5, bnb + li * 5, sWi, sBi, sS);
        slot ^= 1;
        // ---- pass 1: stats(h); 2 rows/thread
#pragma unroll
        for (int q = 0; q < 20; q++) acc[q] = 0ull;
        for (int g = gt0; g < NPAIR; g += TT) {
            ull z[5], h[5];
            loadZ1(g, z, POL);
            aff5r(sWi, sBi, z, h);
            st2(acc, h);
        }
        reduce_store(acc, slot, swr);
        grid_barrier();
        fold_affine(slot, 5, lw + lj * 25, lb + lj * 5, bng + lj * 5, bnb + lj * 5, sWj, sBj, sS);
        if (tid < 25) { float w = skw[blk * 25 + tid]; sSkW[(tid / 5) * 6 + (tid % 5)] = pk(w, w); }
        if (tid < 5)  { float sb = skb[blk * 5 + tid]; sBj[tid] = add2(sBj[tid], pk(sb, sb));
                        sSkW[tid * 6 + 5] = 0ull; }
        __syncthreads();
        slot ^= 1;
        // ---- pass 2: z' = relu(affj(h) + skip(z)); 2 rows/thread
#pragma unroll
        for (int q = 0; q < 20; q++) acc[q] = 0ull;
        for (int g = gt0; g < NPAIR; g += TT) {
            ull z[5];
            loadZ1(g, z, POL);
            // skip partials (z live)
            ull s[5];
#pragma unroll
            for (int o = 0; o < 5; o++) {
                ull w[5]; ldrow(sSkW, o, w);
                ull t = sBj[o];
#pragma unroll
                for (int i2 = 0; i2 < 5; i2++) t = fma2(w[i2], z[i2], t);
                s[o] = t;
            }
            // h (z dead afterward)
            ull h[5];
            aff5r(sWi, sBi, z, h);
            // second affine accumulates into skip partials, then relu
#pragma unroll
            for (int o = 0; o < 5; o++) {
                ull w[5]; ldrow(sWj, o, w);
                ull t = s[o];
#pragma unroll
                for (int i2 = 0; i2 < 5; i2++) t = fma2(w[i2], h[i2], t);
                s[o] = relu2(t);
            }
            storeZ1(g, s, POL);
            st2(acc, s);
        }
        reduce_store(acc, slot, swr);
        grid_barrier();
    }

    // ---- final: fold lin9+bn9, out = lin10(relu(aff9(z))); 2 rows/thread
    fold_affine(slot, 2, l9w, l9b, b9g, b9b, sWi, sBi, sS);
    const float w0 = l10w[0], w1 = l10w[1], c10 = l10b[0];
    const ull W0 = pk(w0, w0), W1 = pk(w1, w1), B10 = pk(c10, c10);
    for (int g = gt0; g < NPAIR; g += TT) {
        ull z[5];
        loadZ1(g, z, POL);
        ull q0 = sBi[0], q1 = sBi[1];
        {
            ull wr0[5], wr1[5];
            ldrow(sWi, 0, wr0); ldrow(sWi, 1, wr1);
#pragma unroll
            for (int i2 = 0; i2 < 5; i2++) {
                q0 = fma2(wr0[i2], z[i2], q0);
                q1 = fma2(wr1[i2], z[i2], q1);
            }
        }
        q0 = relu2(q0); q1 = relu2(q1);
        ull o = fma2(W0, q0, fma2(W1, q1, B10));
        float o0, o1; upk(o, o0, o1);
        *(float2*)&out[2 * (size_t)g] = make_float2(o0, o1);
    }
}

extern "C" void kernel_launch(void* const* d_in, const int* in_sizes, int n_in,
                              void* d_out, int out_size) {
    (void)in_sizes; (void)n_in; (void)out_size;
    net_kernel<<<NBLK, NTHR>>>(
        (const float*)d_in[0],   // x
        (const float*)d_in[1],   // lins_w
        (const float*)d_in[2],   // lins_b
        (const float*)d_in[3],   // skips_w
        (const float*)d_in[4],   // skips_b
        (const float*)d_in[5],   // bn_g
        (const float*)d_in[6],   // bn_b
        (const float*)d_in[7],   // lin9_w
        (const float*)d_in[8],   // lin9_b
        (const float*)d_in[9],   // bn9_g
        (const float*)d_in[10],  // bn9_b
        (const float*)d_in[11],  // lin10_w
        (const float*)d_in[12],  // lin10_b
        (float*)d_out);
}

// round 16
// speedup vs baseline: 1.1450x; 1.1450x over previous
#include <cuda_runtime.h>

typedef unsigned long long ull;

#define NROWS 4194304
#define NGRP  (NROWS/4)
#define NBLK  148
#define NTHR  512
#define TT    (NBLK*NTHR)
#define NWARP (NTHR/32)

// 80 MB activation scratch, SoA: g_Z[f*NROWS + row]
__device__ float g_Z[(size_t)5 * NROWS];
// per-round block partial sums (double-buffered by round parity)
__device__ float g_part[2][NBLK * 20];
__device__ unsigned g_cnt = 0;
__device__ unsigned g_gen = 0;

// ---------------- packed f32x2 helpers ----------------
__device__ __forceinline__ ull pk(float lo, float hi) {
    ull r; asm("mov.b64 %0,{%1,%2};" : "=l"(r) : "f"(lo), "f"(hi)); return r;
}
__device__ __forceinline__ void upk(ull v, float& lo, float& hi) {
    asm("mov.b64 {%0,%1},%2;" : "=f"(lo), "=f"(hi) : "l"(v));
}
__device__ __forceinline__ ull fma2(ull a, ull b, ull c) {
    ull d; asm("fma.rn.f32x2 %0,%1,%2,%3;" : "=l"(d) : "l"(a), "l"(b), "l"(c)); return d;
}
__device__ __forceinline__ ull add2(ull a, ull b) {
    ull d; asm("add.rn.f32x2 %0,%1,%2;" : "=l"(d) : "l"(a), "l"(b)); return d;
}
// relu on both packed halves (no packed max in PTX)
__device__ __forceinline__ ull relu2(ull a) {
    float lo, hi; upk(a, lo, hi);
    return pk(fmaxf(lo, 0.f), fmaxf(hi, 0.f));
}

// ---------------- L2 cache policies (policy-operand form) ----------------
__device__ __forceinline__ ull mkpolicy_evict_last() {
    ull p; asm("createpolicy.fractional.L2::evict_last.b64 %0, 1.0;" : "=l"(p)); return p;
}
__device__ __forceinline__ ull mkpolicy_evict_first() {
    ull p; asm("createpolicy.fractional.L2::evict_first.b64 %0, 1.0;" : "=l"(p)); return p;
}

// ---------------- grid barrier (generation counter, replay-safe) ----------------
__device__ __forceinline__ void grid_barrier() {
    __threadfence();
    __syncthreads();
    if (threadIdx.x == 0) {
        unsigned my = *((volatile unsigned*)&g_gen);
        unsigned t = atomicAdd(&g_cnt, 1u);
        if (t == (unsigned)(NBLK - 1)) {
            g_cnt = 0u;
            __threadfence();
            atomicAdd(&g_gen, 1u);
        } else {
            while (*((volatile unsigned*)&g_gen) == my) { __nanosleep(64); }
        }
    }
    __syncthreads();
    __threadfence();
}

// ---------------- Z load/store (two packed row-pairs = 4 rows), L2-pinned ----------------
__device__ __forceinline__ void loadZ2(int g, ull a[5], ull b[5], ull pol) {
#pragma unroll
    for (int f = 0; f < 5; f++) {
        const ull* p = (const ull*)&g_Z[(size_t)f * NROWS + 4 * (size_t)g];
        asm volatile("ld.global.L2::cache_hint.v2.u64 {%0,%1}, [%2], %3;"
                     : "=l"(a[f]), "=l"(b[f]) : "l"(p), "l"(pol));
    }
}
__device__ __forceinline__ void storeZ2(int g, const ull a[5], const ull b[5], ull pol) {
#pragma unroll
    for (int f = 0; f < 5; f++) {
        ull* p = (ull*)&g_Z[(size_t)f * NROWS + 4 * (size_t)g];
        asm volatile("st.global.L2::cache_hint.v2.u64 [%0], {%1,%2}, %3;"
                     :: "l"(p), "l"(a[f]), "l"(b[f]), "l"(pol) : "memory");
    }
}
__device__ __forceinline__ float4 load_x4_stream(const float4* p, ull pol) {
    float4 v;
    asm volatile("ld.global.nc.L2::cache_hint.v4.f32 {%0,%1,%2,%3}, [%4], %5;"
                 : "=f"(v.x), "=f"(v.y), "=f"(v.z), "=f"(v.w) : "l"(p), "l"(pol));
    return v;
}

// ---------------- stats accumulation: 5 means + 15 upper-tri 2nd moments ----------------
__device__ __forceinline__ void st2(ull acc[20], const ull p[5]) {
#pragma unroll
    for (int i = 0; i < 5; i++) acc[i] = add2(acc[i], p[i]);
    int c = 5;
#pragma unroll
    for (int i = 0; i < 5; i++) {
#pragma unroll
        for (int k = i; k < 5; k++) { acc[c] = fma2(p[i], p[k], acc[c]); c++; }
    }
}

// load one padded weight row (stride 6) as 2xLDS.128 + 1xLDS.64
__device__ __forceinline__ void ldrow(const ull* sW, int j, ull w[5]) {
    const ulonglong2* r = (const ulonglong2*)(sW + j * 6);
    ulonglong2 w01 = r[0], w23 = r[1];
    w[0] = w01.x; w[1] = w01.y; w[2] = w23.x; w[3] = w23.y; w[4] = sW[j * 6 + 4];
}

// DUAL-PAIR affine: one weight-row load serves BOTH packed pairs.
__device__ __forceinline__ void aff5r2(const ull* sW, const ull* sB,
                                       const ull inA[5], const ull inB[5],
                                       ull outA[5], ull outB[5]) {
#pragma unroll
    for (int j = 0; j < 5; j++) {
        ull w[5]; ldrow(sW, j, w);
        ull b = sB[j];
        ull ta = b, tb = b;
#pragma unroll
        for (int i = 0; i < 5; i++) {
            ta = fma2(w[i], inA[i], ta);
            tb = fma2(w[i], inB[i], tb);
        }
        outA[j] = relu2(ta);
        outB[j] = relu2(tb);
    }
}

// ---------------- deterministic block reduction -> g_part[slot] ----------------
__device__ __forceinline__ void reduce_store(ull acc[20], int slot, float (*swr)[20]) {
    int tid = threadIdx.x;
    float a[20];
#pragma unroll
    for (int j = 0; j < 20; j++) { float lo, hi; upk(acc[j], lo, hi); a[j] = lo + hi; }
#pragma unroll
    for (int j = 0; j < 20; j++) {
#pragma unroll
        for (int o = 16; o > 0; o >>= 1) a[j] += __shfl_down_sync(0xffffffffu, a[j], o);
    }
    int w = tid >> 5, l = tid & 31;
    if (l == 0) {
#pragma unroll
        for (int j = 0; j < 20; j++) swr[w][j] = a[j];
    }
    __syncthreads();
    if (tid < 20) {
        float t = 0.f;
#pragma unroll
        for (int k = 0; k < NWARP; k++) t += swr[k][tid];
        g_part[slot][blockIdx.x * 20 + tid] = t;
    }
}

// ---------------- BN fold: exact affine from input stats (writes stride-6 rows) ----------------
__device__ __forceinline__ void fold_affine(
    int slot, int J,
    const float* __restrict__ W, const float* __restrict__ B,
    const float* __restrict__ G, const float* __restrict__ Bt,
    ull* sW, ull* sB, float* sS)
{
    int tid = threadIdx.x;
    if (tid < 20) {
        float t = 0.f;
        for (int k = 0; k < NBLK; k++) t += g_part[slot][k * 20 + tid];
        sS[tid] = t;
    }
    __syncthreads();
    if (tid < J) {
        const double inv = 1.0 / (double)NROWS;
        double m[5], w[5];
#pragma unroll
        for (int i = 0; i < 5; i++) { m[i] = (double)sS[i] * inv; w[i] = (double)W[tid * 5 + i]; }
        double mu = (double)B[tid];
#pragma unroll
        for (int i = 0; i < 5; i++) mu += w[i] * m[i];
        double var = 0.0; int c = 5;
        for (int i = 0; i < 5; i++)
            for (int k = i; k < 5; k++) {
                double C = (double)sS[c] * inv - m[i] * m[k];
                var += (i == k ? w[i] * w[k] : 2.0 * w[i] * w[k]) * C;
                c++;
            }
        double rstd = rsqrt(var + 1e-5);
        float sc = (float)((double)G[tid] * rstd);
#pragma unroll
        for (int i = 0; i < 5; i++) { float wv = W[tid * 5 + i] * sc; sW[tid * 6 + i] = pk(wv, wv); }
        sW[tid * 6 + 5] = 0ull;  // padding (covered by v2 loads, never used)
        float bv = (float)(((double)B[tid] - mu) * rstd * (double)G[tid] + (double)Bt[tid]);
        sB[tid] = pk(bv, bv);
    }
    __syncthreads();
}

// ---------------- the whole net in one persistent kernel ----------------
__global__ void __launch_bounds__(NTHR, 1) net_kernel(
    const float* __restrict__ x,
    const float* __restrict__ lw,  const float* __restrict__ lb,
    const float* __restrict__ skw, const float* __restrict__ skb,
    const float* __restrict__ bng, const float* __restrict__ bnb,
    const float* __restrict__ l9w, const float* __restrict__ l9b,
    const float* __restrict__ b9g, const float* __restrict__ b9b,
    const float* __restrict__ l10w, const float* __restrict__ l10b,
    float* __restrict__ out)
{
    __shared__ ull sWi[30], sBi[5], sWj[30], sBj[5], sSkW[30];
    __shared__ float swr[NWARP][20];
    __shared__ float sS[20];

    const int tid = threadIdx.x;
    const int gt0 = blockIdx.x * NTHR + tid;
    const ull POL = mkpolicy_evict_last();
    const ull POLF = mkpolicy_evict_first();

    ull acc[20];

    // ---- pass 0: transpose x (AoS, streaming) -> g_Z (SoA, pinned) + stats(x)
#pragma unroll
    for (int q = 0; q < 20; q++) acc[q] = 0ull;
    for (int g = gt0; g < NGRP; g += TT) {
        const float4* p = (const float4*)(x + (size_t)20 * g);
        float4 A = load_x4_stream(p + 0, POLF), Bq = load_x4_stream(p + 1, POLF),
               Cq = load_x4_stream(p + 2, POLF), Dq = load_x4_stream(p + 3, POLF),
               Eq = load_x4_stream(p + 4, POLF);
        ull a[5], b[5];
        a[0] = pk(A.x,  Bq.y); a[1] = pk(A.y,  Bq.z); a[2] = pk(A.z,  Bq.w);
        a[3] = pk(A.w,  Cq.x); a[4] = pk(Bq.x, Cq.y);
        b[0] = pk(Cq.z, Dq.w); b[1] = pk(Cq.w, Eq.x); b[2] = pk(Dq.x, Eq.y);
        b[3] = pk(Dq.y, Eq.z); b[4] = pk(Dq.z, Eq.w);
        storeZ2(g, a, b, POL);
        st2(acc, a); st2(acc, b);
    }
    reduce_store(acc, 0, swr);
    grid_barrier();

    int slot = 0;
    for (int blk = 0; blk < 4; blk++) {
        const int li = 2 * blk, lj = li + 1;
        fold_affine(slot, 5, lw + li * 25, lb + li * 5, bng + li * 5, bnb + li * 5, sWi, sBi, sS);
        slot ^= 1;
        // ---- pass 1: stats(h), dual-pair affine (one weight load for both pairs)
#pragma unroll
        for (int q = 0; q < 20; q++) acc[q] = 0ull;
        for (int g = gt0; g < NGRP; g += TT) {
            ull za[5], zb[5], ha[5], hb[5];
            loadZ2(g, za, zb, POL);
            aff5r2(sWi, sBi, za, zb, ha, hb);
            st2(acc, ha); st2(acc, hb);
        }
        reduce_store(acc, slot, swr);
        grid_barrier();
        fold_affine(slot, 5, lw + lj * 25, lb + lj * 5, bng + lj * 5, bnb + lj * 5, sWj, sBj, sS);
        if (tid < 25) { float w = skw[blk * 25 + tid]; sSkW[(tid / 5) * 6 + (tid % 5)] = pk(w, w); }
        if (tid < 5)  { float sb = skb[blk * 5 + tid]; sBj[tid] = add2(sBj[tid], pk(sb, sb));
                        sSkW[tid * 6 + 5] = 0ull; }
        __syncthreads();
        slot ^= 1;
        // ---- pass 2: z' = relu(affj(h) + skip(z)), write Z, stats(z')
#pragma unroll
        for (int q = 0; q < 20; q++) acc[q] = 0ull;
        for (int g = gt0; g < NGRP; g += TT) {
            ull za[5], zb[5];
            loadZ2(g, za, zb, POL);
            // skip partials first (za/zb live); weight row loaded once for both pairs
            ull sa[5], sb2[5];
#pragma unroll
            for (int o = 0; o < 5; o++) {
                ull w[5]; ldrow(sSkW, o, w);
                ull ta = sBj[o], tb = sBj[o];
#pragma unroll
                for (int i2 = 0; i2 < 5; i2++) {
                    ta = fma2(w[i2], za[i2], ta);
                    tb = fma2(w[i2], zb[i2], tb);
                }
                sa[o] = ta; sb2[o] = tb;
            }
            // h (za/zb dead afterward), dual-pair
            ull ha[5], hb[5];
            aff5r2(sWi, sBi, za, zb, ha, hb);
            // second affine accumulates into skip partials, then relu
#pragma unroll
            for (int o = 0; o < 5; o++) {
                ull w[5]; ldrow(sWj, o, w);
                ull ta = sa[o], tb = sb2[o];
#pragma unroll
                for (int i2 = 0; i2 < 5; i2++) {
                    ta = fma2(w[i2], ha[i2], ta);
                    tb = fma2(w[i2], hb[i2], tb);
                }
                sa[o] = relu2(ta); sb2[o] = relu2(tb);
            }
            storeZ2(g, sa, sb2, POL);
            st2(acc, sa); st2(acc, sb2);
        }
        reduce_store(acc, slot, swr);
        grid_barrier();
    }

    // ---- final: fold lin9+bn9 from stats(z), then out = lin10(relu(...))
    fold_affine(slot, 2, l9w, l9b, b9g, b9b, sWi, sBi, sS);
    const float w0 = l10w[0], w1 = l10w[1], c10 = l10b[0];
    const ull W0 = pk(w0, w0), W1 = pk(w1, w1), B10 = pk(c10, c10);
    for (int g = gt0; g < NGRP; g += TT) {
        ull za[5], zb[5];
        loadZ2(g, za, zb, POL);
        ull q0a = sBi[0], q1a = sBi[1], q0b = sBi[0], q1b = sBi[1];
        {
            ull wr0[5], wr1[5];
            ldrow(sWi, 0, wr0); ldrow(sWi, 1, wr1);
#pragma unroll
            for (int i2 = 0; i2 < 5; i2++) {
                q0a = fma2(wr0[i2], za[i2], q0a);
                q1a = fma2(wr1[i2], za[i2], q1a);
                q0b = fma2(wr0[i2], zb[i2], q0b);
                q1b = fma2(wr1[i2], zb[i2], q1b);
            }
        }
        q0a = relu2(q0a); q1a = relu2(q1a); q0b = relu2(q0b); q1b = relu2(q1b);
        ull oa = fma2(W0, q0a, fma2(W1, q1a, B10));
        ull ob = fma2(W0, q0b, fma2(W1, q1b, B10));
        float o0, o1, o2, o3; upk(oa, o0, o1); upk(ob, o2, o3);
        *(float4*)&out[4 * (size_t)g] = make_float4(o0, o1, o2, o3);
    }
}

extern "C" void kernel_launch(void* const* d_in, const int* in_sizes, int n_in,
                              void* d_out, int out_size) {
    (void)in_sizes; (void)n_in; (void)out_size;
    net_kernel<<<NBLK, NTHR>>>(
        (const float*)d_in[0],   // x
        (const float*)d_in[1],   // lins_w
        (const float*)d_in[2],   // lins_b
        (const float*)d_in[3],   // skips_w
        (const float*)d_in[4],   // skips_b
        (const float*)d_in[5],   // bn_g
        (const float*)d_in[6],   // bn_b
        (const float*)d_in[7],   // lin9_w
        (const float*)d_in[8],   // lin9_b
        (const float*)d_in[9],   // bn9_g
        (const float*)d_in[10],  // bn9_b
        (const float*)d_in[11],  // lin10_w
        (const float*)d_in[12],  // lin10_b
        (float*)d_out);
}